// round 5
// baseline (speedup 1.0000x reference)
#include <cuda_runtime.h>
#include <cuda_fp16.h>
#include <cstdint>
#include <cstddef>

// ---------------- problem constants ----------------
#define N_Uc   8192
#define N_Ic   8192
#define D_INc  2048
#define D_Hc   2048
#define N_TOTc (N_Uc + N_Ic)

// ---------------- fp16 scratch (device globals; no allocs allowed) ----------------
__device__ __half g_inputH[(size_t)N_TOTc * D_INc];   // rn(input)  [16384][2048]
__device__ __half g_WH[(size_t)D_Hc * D_INc];         // rn(W)      [2048][2048]
__device__ __half g_adjH[(size_t)N_Uc * N_Ic];        // rn(adj)    [8192][8192]
__device__ __half g_supH[(size_t)N_TOTc * D_Hc];      // rn(support)[16384][2048]

// ---------------- PTX helpers ----------------
__device__ __forceinline__ uint32_t smem_u32(const void* p) {
    uint32_t a;
    asm("{ .reg .u64 t; cvta.to.shared.u64 t, %1; cvt.u32.u64 %0, t; }" : "=r"(a) : "l"(p));
    return a;
}
__device__ __forceinline__ void cp_async16(uint32_t s, const void* g) {
    asm volatile("cp.async.cg.shared.global [%0], [%1], 16;" :: "r"(s), "l"(g));
}
__device__ __forceinline__ void cp_commit() {
    asm volatile("cp.async.commit_group;" ::: "memory");
}
template<int N>
__device__ __forceinline__ void cp_wait() {
    asm volatile("cp.async.wait_group %0;" :: "n"(N) : "memory");
}
__device__ __forceinline__ void ldsm_x4(uint32_t& r0, uint32_t& r1, uint32_t& r2,
                                        uint32_t& r3, uint32_t addr) {
    asm volatile("ldmatrix.sync.aligned.m8n8.x4.shared.b16 {%0,%1,%2,%3}, [%4];"
                 : "=r"(r0), "=r"(r1), "=r"(r2), "=r"(r3) : "r"(addr));
}
__device__ __forceinline__ void ldsm_x4_t(uint32_t& r0, uint32_t& r1, uint32_t& r2,
                                          uint32_t& r3, uint32_t addr) {
    asm volatile("ldmatrix.sync.aligned.m8n8.x4.trans.shared.b16 {%0,%1,%2,%3}, [%4];"
                 : "=r"(r0), "=r"(r1), "=r"(r2), "=r"(r3) : "r"(addr));
}
__device__ __forceinline__ void mma_f16(float d[4], const uint32_t a[4],
                                        const uint32_t b[2], const float c[4]) {
    asm volatile(
        "mma.sync.aligned.m16n8k16.row.col.f32.f16.f16.f32 "
        "{%0,%1,%2,%3}, {%4,%5,%6,%7}, {%8,%9}, {%10,%11,%12,%13};"
        : "=f"(d[0]), "=f"(d[1]), "=f"(d[2]), "=f"(d[3])
        : "r"(a[0]), "r"(a[1]), "r"(a[2]), "r"(a[3]),
          "r"(b[0]), "r"(b[1]),
          "f"(c[0]), "f"(c[1]), "f"(c[2]), "f"(c[3]));
}

// ---------------- GEMM ----------------
//   C[m][n] = epi( sum_k A(m,k)*B(k,n) )
// A(m,k) = A_K_CONTIG ? A[m*lda+k] : A[k*lda+m]   (halves)
// B(k,n) = B_N_CONTIG ? B[k*ldb+n] : B[n*ldb+k]   (halves)
// EPI==0: C (half) [m][ldc] = rn(acc + E[n])      (bias; writes fp16 support)
// EPI==1: C (float)[m][ldc] = acc * E[m]          (degree scale)
// CTA tile 128x256x32, 8 warps (2x4), warp tile 64x64. 3-stage cp.async pipeline.
#define BMh 128
#define BNh 256
#define BKh 32
#define NSTG 3
// smem row strides (bytes), padded +16 for ldmatrix conflict-freedom:
#define SKC  80     // K-contig rows: 32 halves = 64B -> 80
#define SMCA 272    // A M-contig rows: 128 halves = 256B -> 272
#define SMCB 528    // B N-contig rows: 256 halves = 512B -> 528

#define ASZ_(AK) ((AK) ? BMh * SKC : BKh * SMCA)
#define BSZ_(BN) ((BN) ? BKh * SMCB : BNh * SKC)
#define STG_(AK, BN) (ASZ_(AK) + BSZ_(BN))

template<bool A_K_CONTIG, bool B_N_CONTIG, int EPI>
__launch_bounds__(256, 1)
__global__ void hgemm(const __half* __restrict__ A, const __half* __restrict__ B,
                      const float* __restrict__ E, void* __restrict__ Cv,
                      int N, int K, int lda, int ldb, int ldc)
{
    constexpr int ASZ = ASZ_(A_K_CONTIG);
    constexpr int STG = STG_(A_K_CONTIG, B_N_CONTIG);
    extern __shared__ __align__(16) char smem[];
    const uint32_t sb = smem_u32(smem);

    const int tid  = threadIdx.x;
    const int lane = tid & 31;
    const int warp = tid >> 5;
    const int wm   = warp >> 2;          // 0..1  (64 rows)
    const int wn   = warp & 3;           // 0..3  (64 cols)
    const int q    = lane >> 3;          // ldmatrix quad 0..3
    const int r    = lane & 7;
    const int g    = lane >> 2;
    const int t    = lane & 3;

    const int m0 = blockIdx.y * BMh;
    const int n0 = blockIdx.x * BNh;

    float acc[4][8][4];
#pragma unroll
    for (int i = 0; i < 4; i++)
#pragma unroll
        for (int j = 0; j < 8; j++)
#pragma unroll
            for (int k = 0; k < 4; k++) acc[i][j][k] = 0.f;

    // -------- per-thread ldmatrix base offsets (bytes, within panel) --------
    uint32_t a_base, b_base;
    if (A_K_CONTIG)
        a_base = (uint32_t)((wm * 64 + r + (q & 1) * 8) * SKC + (q >> 1) * 16);
    else
        a_base = (uint32_t)((r + (q >> 1) * 8) * SMCA + (wm * 64 + (q & 1) * 8) * 2);
    if (B_N_CONTIG)
        b_base = (uint32_t)((r + (q & 1) * 8) * SMCB + (wn * 64 + (q >> 1) * 8) * 2);
    else
        b_base = (uint32_t)((wn * 64 + r + (q >> 1) * 8) * SKC + (q & 1) * 16);

    // -------- stage fill (cp.async, 16B chunks) --------
    auto fill = [&](int s, int kt) {
        const uint32_t ab = sb + (uint32_t)s * STG;
        const uint32_t bb = ab + ASZ;
        const int k0 = kt * BKh;
        if (A_K_CONTIG) {   // 128 rows x 4 chunks = 512
#pragma unroll
            for (int i = 0; i < 2; i++) {
                int ci = tid + i * 256, row = ci >> 2, c = ci & 3;
                cp_async16(ab + row * SKC + c * 16,
                           A + (size_t)(m0 + row) * lda + k0 + c * 8);
            }
        } else {            // 32 k-rows x 16 chunks = 512
#pragma unroll
            for (int i = 0; i < 2; i++) {
                int ci = tid + i * 256, row = ci >> 4, c = ci & 15;
                cp_async16(ab + row * SMCA + c * 16,
                           A + (size_t)(k0 + row) * lda + m0 + c * 8);
            }
        }
        if (B_N_CONTIG) {   // 32 k-rows x 32 chunks = 1024
#pragma unroll
            for (int i = 0; i < 4; i++) {
                int ci = tid + i * 256, row = ci >> 5, c = ci & 31;
                cp_async16(bb + row * SMCB + c * 16,
                           B + (size_t)(k0 + row) * ldb + n0 + c * 8);
            }
        } else {            // 256 n-rows x 4 chunks = 1024
#pragma unroll
            for (int i = 0; i < 4; i++) {
                int ci = tid + i * 256, row = ci >> 2, c = ci & 3;
                cp_async16(bb + row * SKC + c * 16,
                           B + (size_t)(n0 + row) * ldb + k0 + c * 8);
            }
        }
        cp_commit();
    };

    const int T = K / BKh;
    fill(0, 0);
    fill(1, 1);

    int s = 0;
    for (int kt = 0; kt < T; kt++) {
        if (kt + 2 < T) {
            int ns = s + 2; if (ns >= NSTG) ns -= NSTG;
            fill(ns, kt + 2);
        } else {
            cp_commit();
        }
        cp_wait<2>();
        __syncthreads();

        const uint32_t ab = sb + (uint32_t)s * STG;
        const uint32_t bb = ab + ASZ;
        const uint32_t aa = ab + a_base;
        const uint32_t ba = bb + b_base;

#pragma unroll
        for (int ks = 0; ks < 2; ks++) {   // two k16 steps per stage
            const uint32_t ak = A_K_CONTIG ? (aa + ks * 32) : (aa + ks * 16 * SMCA);
            const uint32_t bk = B_N_CONTIG ? (ba + ks * 16 * SMCB) : (ba + ks * 32);

            uint32_t af[4][4];
#pragma unroll
            for (int mt = 0; mt < 4; mt++) {
                const uint32_t addr = A_K_CONTIG ? (ak + mt * 16 * SKC) : (ak + mt * 32);
                if (A_K_CONTIG) ldsm_x4  (af[mt][0], af[mt][1], af[mt][2], af[mt][3], addr);
                else            ldsm_x4_t(af[mt][0], af[mt][1], af[mt][2], af[mt][3], addr);
            }
            uint32_t bf[8][2];
#pragma unroll
            for (int h = 0; h < 4; h++) {  // 4 x4 loads cover 8 n-tiles (n64)
                const uint32_t addr = B_N_CONTIG ? (bk + h * 32) : (bk + h * 16 * SKC);
                if (B_N_CONTIG) ldsm_x4_t(bf[2*h][0], bf[2*h][1], bf[2*h+1][0], bf[2*h+1][1], addr);
                else            ldsm_x4  (bf[2*h][0], bf[2*h][1], bf[2*h+1][0], bf[2*h+1][1], addr);
            }
#pragma unroll
            for (int mt = 0; mt < 4; mt++)
#pragma unroll
                for (int nt = 0; nt < 8; nt++)
                    mma_f16(acc[mt][nt], af[mt], bf[nt], acc[mt][nt]);
        }
        __syncthreads();
        if (++s == NSTG) s = 0;
    }

    // -------- epilogue --------
#pragma unroll
    for (int mt = 0; mt < 4; mt++) {
        const int mr0 = m0 + wm * 64 + mt * 16 + g;
        const int mr1 = mr0 + 8;
        float s0 = 1.f, s1 = 1.f;
        if (EPI == 1) { s0 = E[mr0]; s1 = E[mr1]; }
#pragma unroll
        for (int nt = 0; nt < 8; nt++) {
            const int nc = n0 + wn * 64 + nt * 8 + 2 * t;
            if (EPI == 0) {
                __half* C = (__half*)Cv;
                const float bx = E[nc], by = E[nc + 1];
                *reinterpret_cast<__half2*>(&C[(size_t)mr0 * ldc + nc]) =
                    __floats2half2_rn(acc[mt][nt][0] + bx, acc[mt][nt][1] + by);
                *reinterpret_cast<__half2*>(&C[(size_t)mr1 * ldc + nc]) =
                    __floats2half2_rn(acc[mt][nt][2] + bx, acc[mt][nt][3] + by);
            } else {
                float* C = (float*)Cv;
                float2 v0 = make_float2(acc[mt][nt][0] * s0, acc[mt][nt][1] * s0);
                float2 v1 = make_float2(acc[mt][nt][2] * s1, acc[mt][nt][3] * s1);
                *reinterpret_cast<float2*>(&C[(size_t)mr0 * ldc + nc]) = v0;
                *reinterpret_cast<float2*>(&C[(size_t)mr1 * ldc + nc]) = v1;
            }
        }
    }
}

// ---------------- fp32 -> fp16 pre-pass ----------------
__global__ void f32_to_f16(const float* __restrict__ src, __half* __restrict__ dst) {
    size_t i = ((size_t)blockIdx.x * blockDim.x + threadIdx.x) * 8;
    float4 v0 = *reinterpret_cast<const float4*>(src + i);
    float4 v1 = *reinterpret_cast<const float4*>(src + i + 4);
    __half2 h0 = __floats2half2_rn(v0.x, v0.y);
    __half2 h1 = __floats2half2_rn(v0.z, v0.w);
    __half2 h2 = __floats2half2_rn(v1.x, v1.y);
    __half2 h3 = __floats2half2_rn(v1.z, v1.w);
    uint4 u;
    u.x = *reinterpret_cast<uint32_t*>(&h0);
    u.y = *reinterpret_cast<uint32_t*>(&h1);
    u.z = *reinterpret_cast<uint32_t*>(&h2);
    u.w = *reinterpret_cast<uint32_t*>(&h3);
    *reinterpret_cast<uint4*>(dst + i) = u;
}

// ---------------- launch ----------------
extern "C" void kernel_launch(void* const* d_in, const int* in_sizes, int n_in,
                              void* d_out, int out_size)
{
    const float* input  = (const float*)d_in[0];
    const float* adj    = (const float*)d_in[1];
    const float* degree = (const float*)d_in[2];
    const float* W      = (const float*)d_in[3];
    const float* b      = (const float*)d_in[4];
    float* out = (float*)d_out;

    __half *inputH, *WH, *adjH, *supH;
    cudaGetSymbolAddress((void**)&inputH, g_inputH);
    cudaGetSymbolAddress((void**)&WH, g_WH);
    cudaGetSymbolAddress((void**)&adjH, g_adjH);
    cudaGetSymbolAddress((void**)&supH, g_supH);

    constexpr int SM1 = NSTG * STG_(1, 0);   // GEMM1: 92160
    constexpr int SM2 = NSTG * STG_(1, 1);   // GEMM2: 81408
    constexpr int SM3 = NSTG * STG_(0, 1);   // GEMM3: 76800
    cudaFuncSetAttribute(hgemm<true, false, 0>, cudaFuncAttributeMaxDynamicSharedMemorySize, SM1);
    cudaFuncSetAttribute(hgemm<true, true, 1>,  cudaFuncAttributeMaxDynamicSharedMemorySize, SM2);
    cudaFuncSetAttribute(hgemm<false, true, 1>, cudaFuncAttributeMaxDynamicSharedMemorySize, SM3);

    // pre-passes: RN-round everything to fp16 once
    f32_to_f16<<<(size_t)N_TOTc * D_INc / (8 * 256), 256>>>(input, inputH);
    f32_to_f16<<<(size_t)D_Hc * D_INc / (8 * 256), 256>>>(W, WH);
    f32_to_f16<<<(size_t)N_Uc * N_Ic / (8 * 256), 256>>>(adj, adjH);

    // GEMM1: supH = rn( input @ W^T + b )  (M=16384, N=2048, K=2048)
    {
        dim3 grid(D_Hc / BNh, N_TOTc / BMh);
        hgemm<true, false, 0><<<grid, 256, SM1>>>(
            inputH, WH, b, supH, D_Hc, D_INc, D_INc, D_INc, D_Hc);
    }
    // GEMM2: out_u = deg_u * (adj @ sup_i)
    {
        dim3 grid(D_Hc / BNh, N_Uc / BMh);
        hgemm<true, true, 1><<<grid, 256, SM2>>>(
            adjH, supH + (size_t)N_Uc * D_Hc, degree, out,
            D_Hc, N_Ic, N_Ic, D_Hc, D_Hc);
    }
    // GEMM3: out_i = deg_i * (adj^T @ sup_u)
    {
        dim3 grid(D_Hc / BNh, N_Ic / BMh);
        hgemm<false, true, 1><<<grid, 256, SM3>>>(
            adjH, supH, degree + N_Uc, out + (size_t)N_Uc * D_Hc,
            D_Hc, N_Uc, N_Ic, D_Hc, D_Hc);
    }
}

// round 6
// speedup vs baseline: 1.2657x; 1.2657x over previous
#include <cuda_runtime.h>
#include <cuda_fp16.h>
#include <cstdint>
#include <cstddef>

// ---------------- problem constants ----------------
#define N_Uc   8192
#define N_Ic   8192
#define D_INc  2048
#define D_Hc   2048
#define N_TOTc (N_Uc + N_Ic)

// ---------------- fp16 scratch (device globals; no allocs allowed) ----------------
__device__ __half g_inputH[(size_t)N_TOTc * D_INc];   // rn(input)  [16384][2048]
__device__ __half g_WH[(size_t)D_Hc * D_INc];         // rn(W)      [2048][2048]
__device__ __half g_adjH[(size_t)N_Uc * N_Ic];        // rn(adj)    [8192][8192]
__device__ __half g_supH[(size_t)N_TOTc * D_Hc];      // rn(support)[16384][2048]

// ---------------- PTX helpers ----------------
__device__ __forceinline__ uint32_t smem_u32(const void* p) {
    uint32_t a;
    asm("{ .reg .u64 t; cvta.to.shared.u64 t, %1; cvt.u32.u64 %0, t; }" : "=r"(a) : "l"(p));
    return a;
}
__device__ __forceinline__ void cp_async16(uint32_t s, const void* g) {
    asm volatile("cp.async.cg.shared.global [%0], [%1], 16;" :: "r"(s), "l"(g));
}
__device__ __forceinline__ void cp_commit() {
    asm volatile("cp.async.commit_group;" ::: "memory");
}
template<int N>
__device__ __forceinline__ void cp_wait() {
    asm volatile("cp.async.wait_group %0;" :: "n"(N) : "memory");
}
__device__ __forceinline__ void ldsm_x4(uint32_t& r0, uint32_t& r1, uint32_t& r2,
                                        uint32_t& r3, uint32_t addr) {
    asm volatile("ldmatrix.sync.aligned.m8n8.x4.shared.b16 {%0,%1,%2,%3}, [%4];"
                 : "=r"(r0), "=r"(r1), "=r"(r2), "=r"(r3) : "r"(addr));
}
__device__ __forceinline__ void ldsm_x4_t(uint32_t& r0, uint32_t& r1, uint32_t& r2,
                                          uint32_t& r3, uint32_t addr) {
    asm volatile("ldmatrix.sync.aligned.m8n8.x4.trans.shared.b16 {%0,%1,%2,%3}, [%4];"
                 : "=r"(r0), "=r"(r1), "=r"(r2), "=r"(r3) : "r"(addr));
}
__device__ __forceinline__ void mma_f16(float d[4], const uint32_t a[4],
                                        const uint32_t b[2], const float c[4]) {
    asm volatile(
        "mma.sync.aligned.m16n8k16.row.col.f32.f16.f16.f32 "
        "{%0,%1,%2,%3}, {%4,%5,%6,%7}, {%8,%9}, {%10,%11,%12,%13};"
        : "=f"(d[0]), "=f"(d[1]), "=f"(d[2]), "=f"(d[3])
        : "r"(a[0]), "r"(a[1]), "r"(a[2]), "r"(a[3]),
          "r"(b[0]), "r"(b[1]),
          "f"(c[0]), "f"(c[1]), "f"(c[2]), "f"(c[3]));
}

// ---------------- GEMM ----------------
//   C[m][n] = epi( sum_k A(m,k)*B(k,n) )
// A(m,k) = A_K_CONTIG ? A[m*lda+k] : A[k*lda+m]   (halves)
// B(k,n) = B_N_CONTIG ? B[k*ldb+n] : B[n*ldb+k]   (halves)
// EPI==0: C (half) [m][ldc] = rn(acc + E[n])      (bias; writes fp16 support)
// EPI==1: C (float)[m][ldc] = acc * E[m]          (degree scale)
// CTA tile 128x128x32, 8 warps (2x4), warp tile 64x32.
// 4-stage cp.async pipeline, 2 CTAs/SM (CTA-level overlap of barriers/epilogue).
#define BMh 128
#define BNh 128
#define BKh 32
#define NSTG 4
// smem row strides (bytes), padded +16 for ldmatrix conflict-freedom:
#define SKC 80      // K-contig rows: 32 halves = 64B -> 80
#define SMC 272     // MN-contig rows: 128 halves = 256B -> 272

#define ASZ_(AK) ((AK) ? BMh * SKC : BKh * SMC)
#define BSZ_(BN) ((BN) ? BKh * SMC : BNh * SKC)
#define STG_(AK, BN) (ASZ_(AK) + BSZ_(BN))

template<bool A_K_CONTIG, bool B_N_CONTIG, int EPI>
__launch_bounds__(256, 2)
__global__ void hgemm(const __half* __restrict__ A, const __half* __restrict__ B,
                      const float* __restrict__ E, void* __restrict__ Cv,
                      int N, int K, int lda, int ldb, int ldc)
{
    constexpr int ASZ = ASZ_(A_K_CONTIG);
    constexpr int STG = STG_(A_K_CONTIG, B_N_CONTIG);
    extern __shared__ __align__(16) char smem[];
    const uint32_t sb = smem_u32(smem);

    const int tid  = threadIdx.x;
    const int lane = tid & 31;
    const int warp = tid >> 5;
    const int wm   = warp >> 2;          // 0..1  (64 rows)
    const int wn   = warp & 3;           // 0..3  (32 cols)
    const int q    = lane >> 3;          // ldmatrix quad 0..3
    const int r    = lane & 7;
    const int g    = lane >> 2;
    const int t    = lane & 3;

    const int m0 = blockIdx.y * BMh;
    const int n0 = blockIdx.x * BNh;

    float acc[4][4][4];
#pragma unroll
    for (int i = 0; i < 4; i++)
#pragma unroll
        for (int j = 0; j < 4; j++)
#pragma unroll
            for (int k = 0; k < 4; k++) acc[i][j][k] = 0.f;

    // -------- per-thread ldmatrix base offsets (bytes, within panel) --------
    uint32_t a_base, b_base;
    if (A_K_CONTIG)
        a_base = (uint32_t)((wm * 64 + r + (q & 1) * 8) * SKC + (q >> 1) * 16);
    else
        a_base = (uint32_t)((r + (q >> 1) * 8) * SMC + (wm * 64 + (q & 1) * 8) * 2);
    if (B_N_CONTIG)
        b_base = (uint32_t)((r + (q & 1) * 8) * SMC + (wn * 32 + (q >> 1) * 8) * 2);
    else
        b_base = (uint32_t)((wn * 32 + r + (q >> 1) * 8) * SKC + (q & 1) * 16);

    // -------- stage fill (cp.async, 16B chunks) --------
    auto fill = [&](int s, int kt) {
        const uint32_t ab = sb + (uint32_t)s * STG;
        const uint32_t bb = ab + ASZ;
        const int k0 = kt * BKh;
        if (A_K_CONTIG) {   // 128 rows x 4 chunks = 512
#pragma unroll
            for (int i = 0; i < 2; i++) {
                int ci = tid + i * 256, row = ci >> 2, c = ci & 3;
                cp_async16(ab + row * SKC + c * 16,
                           A + (size_t)(m0 + row) * lda + k0 + c * 8);
            }
        } else {            // 32 k-rows x 16 chunks = 512
#pragma unroll
            for (int i = 0; i < 2; i++) {
                int ci = tid + i * 256, row = ci >> 4, c = ci & 15;
                cp_async16(ab + row * SMC + c * 16,
                           A + (size_t)(k0 + row) * lda + m0 + c * 8);
            }
        }
        if (B_N_CONTIG) {   // 32 k-rows x 16 chunks = 512
#pragma unroll
            for (int i = 0; i < 2; i++) {
                int ci = tid + i * 256, row = ci >> 4, c = ci & 15;
                cp_async16(bb + row * SMC + c * 16,
                           B + (size_t)(k0 + row) * ldb + n0 + c * 8);
            }
        } else {            // 128 n-rows x 4 chunks = 512
#pragma unroll
            for (int i = 0; i < 2; i++) {
                int ci = tid + i * 256, row = ci >> 2, c = ci & 3;
                cp_async16(bb + row * SKC + c * 16,
                           B + (size_t)(n0 + row) * ldb + k0 + c * 8);
            }
        }
        cp_commit();
    };

    const int T = K / BKh;
    fill(0, 0);
    fill(1, 1);
    fill(2, 2);

    int s = 0;
    for (int kt = 0; kt < T; kt++) {
        if (kt + 3 < T) {
            int ns = s + 3; if (ns >= NSTG) ns -= NSTG;
            fill(ns, kt + 3);
        } else {
            cp_commit();   // keep outstanding-group count uniform
        }
        cp_wait<3>();
        __syncthreads();

        const uint32_t ab = sb + (uint32_t)s * STG;
        const uint32_t bb = ab + ASZ;
        const uint32_t aa = ab + a_base;
        const uint32_t ba = bb + b_base;

#pragma unroll
        for (int ks = 0; ks < 2; ks++) {   // two k16 steps per stage
            const uint32_t ak = A_K_CONTIG ? (aa + ks * 32) : (aa + ks * 16 * SMC);
            const uint32_t bk = B_N_CONTIG ? (ba + ks * 16 * SMC) : (ba + ks * 32);

            uint32_t af[4][4];
#pragma unroll
            for (int mt = 0; mt < 4; mt++) {
                const uint32_t addr = A_K_CONTIG ? (ak + mt * 16 * SKC) : (ak + mt * 32);
                if (A_K_CONTIG) ldsm_x4  (af[mt][0], af[mt][1], af[mt][2], af[mt][3], addr);
                else            ldsm_x4_t(af[mt][0], af[mt][1], af[mt][2], af[mt][3], addr);
            }
            uint32_t bf[4][2];
#pragma unroll
            for (int h = 0; h < 2; h++) {  // 2 x4 loads cover 4 n-tiles
                const uint32_t addr = B_N_CONTIG ? (bk + h * 32) : (bk + h * 16 * SKC);
                if (B_N_CONTIG) ldsm_x4_t(bf[2*h][0], bf[2*h][1], bf[2*h+1][0], bf[2*h+1][1], addr);
                else            ldsm_x4  (bf[2*h][0], bf[2*h][1], bf[2*h+1][0], bf[2*h+1][1], addr);
            }
#pragma unroll
            for (int mt = 0; mt < 4; mt++)
#pragma unroll
                for (int nt = 0; nt < 4; nt++)
                    mma_f16(acc[mt][nt], af[mt], bf[nt], acc[mt][nt]);
        }
        __syncthreads();
        if (++s == NSTG) s = 0;
    }

    // -------- epilogue --------
#pragma unroll
    for (int mt = 0; mt < 4; mt++) {
        const int mr0 = m0 + wm * 64 + mt * 16 + g;
        const int mr1 = mr0 + 8;
        float s0 = 1.f, s1 = 1.f;
        if (EPI == 1) { s0 = E[mr0]; s1 = E[mr1]; }
#pragma unroll
        for (int nt = 0; nt < 4; nt++) {
            const int nc = n0 + wn * 32 + nt * 8 + 2 * t;
            if (EPI == 0) {
                __half* C = (__half*)Cv;
                const float bx = E[nc], by = E[nc + 1];
                *reinterpret_cast<__half2*>(&C[(size_t)mr0 * ldc + nc]) =
                    __floats2half2_rn(acc[mt][nt][0] + bx, acc[mt][nt][1] + by);
                *reinterpret_cast<__half2*>(&C[(size_t)mr1 * ldc + nc]) =
                    __floats2half2_rn(acc[mt][nt][2] + bx, acc[mt][nt][3] + by);
            } else {
                float* C = (float*)Cv;
                float2 v0 = make_float2(acc[mt][nt][0] * s0, acc[mt][nt][1] * s0);
                float2 v1 = make_float2(acc[mt][nt][2] * s1, acc[mt][nt][3] * s1);
                *reinterpret_cast<float2*>(&C[(size_t)mr0 * ldc + nc]) = v0;
                *reinterpret_cast<float2*>(&C[(size_t)mr1 * ldc + nc]) = v1;
            }
        }
    }
}

// ---------------- fp32 -> fp16 pre-pass ----------------
__global__ void f32_to_f16(const float* __restrict__ src, __half* __restrict__ dst) {
    size_t i = ((size_t)blockIdx.x * blockDim.x + threadIdx.x) * 8;
    float4 v0 = *reinterpret_cast<const float4*>(src + i);
    float4 v1 = *reinterpret_cast<const float4*>(src + i + 4);
    __half2 h0 = __floats2half2_rn(v0.x, v0.y);
    __half2 h1 = __floats2half2_rn(v0.z, v0.w);
    __half2 h2 = __floats2half2_rn(v1.x, v1.y);
    __half2 h3 = __floats2half2_rn(v1.z, v1.w);
    uint4 u;
    u.x = *reinterpret_cast<uint32_t*>(&h0);
    u.y = *reinterpret_cast<uint32_t*>(&h1);
    u.z = *reinterpret_cast<uint32_t*>(&h2);
    u.w = *reinterpret_cast<uint32_t*>(&h3);
    *reinterpret_cast<uint4*>(dst + i) = u;
}

// ---------------- launch ----------------
extern "C" void kernel_launch(void* const* d_in, const int* in_sizes, int n_in,
                              void* d_out, int out_size)
{
    const float* input  = (const float*)d_in[0];
    const float* adj    = (const float*)d_in[1];
    const float* degree = (const float*)d_in[2];
    const float* W      = (const float*)d_in[3];
    const float* b      = (const float*)d_in[4];
    float* out = (float*)d_out;

    __half *inputH, *WH, *adjH, *supH;
    cudaGetSymbolAddress((void**)&inputH, g_inputH);
    cudaGetSymbolAddress((void**)&WH, g_WH);
    cudaGetSymbolAddress((void**)&adjH, g_adjH);
    cudaGetSymbolAddress((void**)&supH, g_supH);

    constexpr int SM1 = NSTG * STG_(1, 0);   // 4 * 20480 = 81920
    constexpr int SM2 = NSTG * STG_(1, 1);   // 4 * 18944 = 75776
    constexpr int SM3 = NSTG * STG_(0, 1);   // 4 * 17408 = 69632
    cudaFuncSetAttribute(hgemm<true, false, 0>, cudaFuncAttributeMaxDynamicSharedMemorySize, SM1);
    cudaFuncSetAttribute(hgemm<true, true, 1>,  cudaFuncAttributeMaxDynamicSharedMemorySize, SM2);
    cudaFuncSetAttribute(hgemm<false, true, 1>, cudaFuncAttributeMaxDynamicSharedMemorySize, SM3);

    // pre-passes: RN-round everything to fp16 once
    f32_to_f16<<<(size_t)N_TOTc * D_INc / (8 * 256), 256>>>(input, inputH);
    f32_to_f16<<<(size_t)D_Hc * D_INc / (8 * 256), 256>>>(W, WH);
    f32_to_f16<<<(size_t)N_Uc * N_Ic / (8 * 256), 256>>>(adj, adjH);

    // GEMM1: supH = rn( input @ W^T + b )  (M=16384, N=2048, K=2048)
    {
        dim3 grid(D_Hc / BNh, N_TOTc / BMh);
        hgemm<true, false, 0><<<grid, 256, SM1>>>(
            inputH, WH, b, supH, D_Hc, D_INc, D_INc, D_INc, D_Hc);
    }
    // GEMM2: out_u = deg_u * (adj @ sup_i)
    {
        dim3 grid(D_Hc / BNh, N_Uc / BMh);
        hgemm<true, true, 1><<<grid, 256, SM2>>>(
            adjH, supH + (size_t)N_Uc * D_Hc, degree, out,
            D_Hc, N_Ic, N_Ic, D_Hc, D_Hc);
    }
    // GEMM3: out_i = deg_i * (adj^T @ sup_u)
    {
        dim3 grid(D_Hc / BNh, N_Ic / BMh);
        hgemm<false, true, 1><<<grid, 256, SM3>>>(
            adjH, supH, degree + N_Uc, out + (size_t)N_Uc * D_Hc,
            D_Hc, N_Uc, N_Ic, D_Hc, D_Hc);
    }
}